// round 15
// baseline (speedup 1.0000x reference)
#include <cuda_runtime.h>
#include <cuda_fp16.h>
#include <cstdint>

#define BATCH 2
#define SEQ   2048
#define HID   1024
#define NHEAD 16
#define HDIM  64
#define NTOK  (BATCH*SEQ)

// ---------------- device scratch (allocation-free rule) ----------------
__device__ __half g_xh   [NTOK * HID];          // x fp16 [M][K]
__device__ __half g_w1t  [3 * HID * HID];       // w_qkv^T fp16 [N=3072][K=1024]
__device__ __half g_w2t  [HID * HID];           // w_out^T fp16 [N=1024][K=1024]
__device__ __half g_qkvh [NTOK * 2 * HID];      // Q,K halves fp16 [tok][2048]
__device__ __half g_vt   [BATCH * NHEAD * HDIM * SEQ];  // V^T fp16 [(b,h,d)][s]
__device__ __half g_attnh[NTOK * HID];          // attn out fp16 [tok][1024]

// ---------------------------------------------------------------------------
__device__ __forceinline__ float ex2(float x) {
    float y;
    asm("ex2.approx.ftz.f32 %0, %1;" : "=f"(y) : "f"(x));
    return y;
}
__device__ __forceinline__ __half2 h2ex2(__half2 x) {
    uint32_t xi = *reinterpret_cast<uint32_t*>(&x);
    uint32_t yi;
    asm("ex2.approx.f16x2 %0, %1;" : "=r"(yi) : "r"(xi));
    return *reinterpret_cast<__half2*>(&yi);
}
__device__ __forceinline__ uint32_t smem_u32(const void* p) {
    return (uint32_t)__cvta_generic_to_shared(p);
}
#define CP16(dst_u32, src_ptr) \
    asm volatile("cp.async.ca.shared.global [%0], [%1], 16;" :: "r"(dst_u32), "l"(src_ptr))
#define CP_COMMIT() asm volatile("cp.async.commit_group;")
#define CP_WAIT0()  asm volatile("cp.async.wait_group 0;")

// fp16 mma: D(f32) = A(f16) * B(f16) + D, m16n8k16
__device__ __forceinline__ void mma16(float* c,
                                      uint32_t a0, uint32_t a1, uint32_t a2, uint32_t a3,
                                      uint32_t b0, uint32_t b1) {
    asm volatile(
        "mma.sync.aligned.m16n8k16.row.col.f32.f16.f16.f32 "
        "{%0,%1,%2,%3}, {%4,%5,%6,%7}, {%8,%9}, {%0,%1,%2,%3};"
        : "+f"(c[0]), "+f"(c[1]), "+f"(c[2]), "+f"(c[3])
        : "r"(a0), "r"(a1), "r"(a2), "r"(a3), "r"(b0), "r"(b1));
}
__device__ __forceinline__ uint32_t ldh2(const __half* p) {
    return *reinterpret_cast<const uint32_t*>(p);
}

// ---------------------------------------------------------------------------
// prepass 1: x fp32 -> fp16
// ---------------------------------------------------------------------------
__global__ void conv_h_kernel(const float* __restrict__ in, __half* __restrict__ out, int n4)
{
    int i = blockIdx.x * blockDim.x + threadIdx.x;
    if (i >= n4) return;
    float4 v = reinterpret_cast<const float4*>(in)[i];
    __half2 h0 = __float22half2_rn(make_float2(v.x, v.y));
    __half2 h1 = __float22half2_rn(make_float2(v.z, v.w));
    reinterpret_cast<uint2*>(out)[i] =
        make_uint2(*reinterpret_cast<uint32_t*>(&h0), *reinterpret_cast<uint32_t*>(&h1));
}

// prepass 2: w fp32 [K][N] -> fp16 [N][K] (transpose)
__global__ void transpose_h_kernel(const float* __restrict__ in, __half* __restrict__ out,
                                   int K, int N)
{
    __shared__ float t[32][33];
    const int n0 = blockIdx.x * 32, k0 = blockIdx.y * 32;
    const int tx = threadIdx.x & 31, ty = threadIdx.x >> 5;   // 32 x 8
    #pragma unroll
    for (int i = 0; i < 4; i++)
        t[ty + i * 8][tx] = in[(size_t)(k0 + ty + i * 8) * N + n0 + tx];
    __syncthreads();
    #pragma unroll
    for (int i = 0; i < 4; i++)
        out[(size_t)(n0 + ty + i * 8) * K + k0 + tx] = __float2half_rn(t[tx][ty + i * 8]);
}

// ---------------------------------------------------------------------------
// FP16 GEMM: C[M,N] = A[M,K](f16,K-major) x Bt[N,K](f16,K-major) + bias.
// CTA tile 128x256, BK=64, 256 threads (8 warps 2x4, 64x64 warp tiles),
// 2-stage cp.async, 1 barrier/iter.  (unchanged from R13)
// ---------------------------------------------------------------------------
#define GAH 72
#define GBH 72
#define STAGE_H (128*GAH + 256*GBH)            // halfs per stage = 27648
#define GEMM_SMEM (2 * STAGE_H * 2)            // 110592 B

__global__ __launch_bounds__(256, 1) void gemm_h(
    const __half* __restrict__ A, const __half* __restrict__ Bt,
    const float* __restrict__ bias,
    float* __restrict__ Cf, __half* __restrict__ Ch, __half* __restrict__ vt,
    int M, int N, int K, int mode)
{
    extern __shared__ __half smh[];

    const int tid  = threadIdx.x;
    const int warp = tid >> 5, lane = tid & 31;
    const int wm = warp >> 2, wn = warp & 3;   // 2 x 4 warp grid -> 64x64 tiles
    const int g2 = lane >> 2, t4 = lane & 3;
    const int cRow = blockIdx.y, cCol = blockIdx.x;

    const __half* Ab = A + (size_t)cRow * 128 * K;
    const __half* Bb = Bt + (size_t)cCol * 256 * K;

    float c[4][8][4];
    #pragma unroll
    for (int mf = 0; mf < 4; mf++)
        #pragma unroll
        for (int nf = 0; nf < 8; nf++)
            #pragma unroll
            for (int i = 0; i < 4; i++) c[mf][nf][i] = 0.f;

    const int nk = K >> 6;    // BK=64

    // prologue: prefetch stage 0
    {
        __half* Ad = smh;
        __half* Bd = smh + 128 * GAH;
        #pragma unroll
        for (int i = 0; i < 4; i++) {                 // A: 128 rows x 8 pieces
            int idx = tid + i * 256;
            int r = idx >> 3, p = idx & 7;
            CP16(smem_u32(Ad + r * GAH + p * 8), Ab + (size_t)r * K + p * 8);
        }
        #pragma unroll
        for (int i = 0; i < 8; i++) {                 // B: 256 rows x 8 pieces
            int idx = tid + i * 256;
            int r = idx >> 3, p = idx & 7;
            CP16(smem_u32(Bd + r * GBH + p * 8), Bb + (size_t)r * K + p * 8);
        }
        CP_COMMIT();
    }

    for (int it = 0; it < nk; it++) {
        CP_WAIT0();
        __syncthreads();

        if (it + 1 < nk) {
            const int k0 = (it + 1) << 6;
            __half* Ad = smh + ((it + 1) & 1) * STAGE_H;
            __half* Bd = Ad + 128 * GAH;
            #pragma unroll
            for (int i = 0; i < 4; i++) {
                int idx = tid + i * 256;
                int r = idx >> 3, p = idx & 7;
                CP16(smem_u32(Ad + r * GAH + p * 8), Ab + (size_t)r * K + k0 + p * 8);
            }
            #pragma unroll
            for (int i = 0; i < 8; i++) {
                int idx = tid + i * 256;
                int r = idx >> 3, p = idx & 7;
                CP16(smem_u32(Bd + r * GBH + p * 8), Bb + (size_t)r * K + k0 + p * 8);
            }
            CP_COMMIT();
        }

        const __half* Ac = smh + (it & 1) * STAGE_H;
        const __half* Bc = Ac + 128 * GAH;

        #pragma unroll
        for (int ks = 0; ks < 4; ks++) {          // 4 x k16 = BK 64
            const int k = ks * 16;
            uint32_t a[4][4], b[8][2];
            #pragma unroll
            for (int mf = 0; mf < 4; mf++) {
                int r0 = wm * 64 + mf * 16 + g2;
                a[mf][0] = ldh2(Ac + r0 * GAH + k + 2 * t4);
                a[mf][1] = ldh2(Ac + (r0 + 8) * GAH + k + 2 * t4);
                a[mf][2] = ldh2(Ac + r0 * GAH + k + 2 * t4 + 8);
                a[mf][3] = ldh2(Ac + (r0 + 8) * GAH + k + 2 * t4 + 8);
            }
            #pragma unroll
            for (int nf = 0; nf < 8; nf++) {
                int cc = wn * 64 + nf * 8 + g2;
                b[nf][0] = ldh2(Bc + cc * GBH + k + 2 * t4);
                b[nf][1] = ldh2(Bc + cc * GBH + k + 2 * t4 + 8);
            }
            #pragma unroll
            for (int mf = 0; mf < 4; mf++)
                #pragma unroll
                for (int nf = 0; nf < 8; nf++)
                    mma16(c[mf][nf], a[mf][0], a[mf][1], a[mf][2], a[mf][3],
                          b[nf][0], b[nf][1]);
        }
    }

    // epilogue
    #pragma unroll
    for (int nf = 0; nf < 8; nf++) {
        int col = cCol * 256 + wn * 64 + nf * 8 + t4 * 2;
        float b0 = bias[col], b1 = bias[col + 1];
        #pragma unroll
        for (int mf = 0; mf < 4; mf++) {
            int r0 = cRow * 128 + wm * 64 + mf * 16 + g2;
            float v00 = c[mf][nf][0] + b0, v01 = c[mf][nf][1] + b1;
            float v10 = c[mf][nf][2] + b0, v11 = c[mf][nf][3] + b1;
            if (mode == 0) {
                *reinterpret_cast<float2*>(Cf + (size_t)r0 * N + col)       = make_float2(v00, v01);
                *reinterpret_cast<float2*>(Cf + (size_t)(r0 + 8) * N + col) = make_float2(v10, v11);
            } else {
                if (col < 2048) {     // Q,K -> qkvh fp16 [tok][2048]
                    __half2 h0 = __float22half2_rn(make_float2(v00, v01));
                    __half2 h1 = __float22half2_rn(make_float2(v10, v11));
                    *reinterpret_cast<__half2*>(Ch + (size_t)r0 * 2048 + col)       = h0;
                    *reinterpret_cast<__half2*>(Ch + (size_t)(r0 + 8) * 2048 + col) = h1;
                } else {              // V -> vt transposed [(b,h,d)][s]
                    int hh = (col - 2048) >> 6, d = (col - 2048) & 63;
                    int b0i = r0 >> 11, s0 = r0 & 2047;
                    int b1i = (r0 + 8) >> 11, s1 = (r0 + 8) & 2047;
                    size_t base0 = ((size_t)(b0i * NHEAD + hh) * HDIM + d) * SEQ;
                    size_t base1 = ((size_t)(b1i * NHEAD + hh) * HDIM + d) * SEQ;
                    vt[base0 + s0]       = __float2half_rn(v00);
                    vt[base0 + SEQ + s0] = __float2half_rn(v01);
                    vt[base1 + s1]       = __float2half_rn(v10);
                    vt[base1 + SEQ + s1] = __float2half_rn(v11);
                }
            }
        }
    }
}

// ---------------------------------------------------------------------------
// FP16 causal flash attention: BQ=128, BKV=64, 256 threads (8 warps).
// P = ex2.approx.f16x2 (half the MUFU ops); l sums the SAME fp16 P values
// used by the PV mma (self-consistent normalization).
// ---------------------------------------------------------------------------
#define BQ  128
#define BKV 64
#define QH_S 72
#define KH_S 72
#define VH_S 72
#define PH_S 72
#define SCALE_L2E 0.18033688011112042f   // 0.125 * log2(e)
#define FLASH_SMEM ((128*QH_S + 2*64*KH_S + 2*64*VH_S + 128*PH_S) * 2)  // 73728 B

__global__ __launch_bounds__(256, 1) void flash_h(
    const __half* __restrict__ qkvh, const __half* __restrict__ vt,
    __half* __restrict__ attn_out)
{
    extern __shared__ __half smh[];
    __half* Qs  = smh;                      // [128][72]
    __half* Ks  = Qs + 128 * QH_S;          // [2][64][72]
    __half* Vst = Ks + 2 * 64 * KH_S;       // [2][64][72]  (Vst[d][kv])
    __half* Ps  = Vst + 2 * 64 * VH_S;      // [128][72]

    const int qb = gridDim.x - 1 - blockIdx.x;   // heavy blocks first
    const int h = blockIdx.y, b = blockIdx.z;
    const int tid = threadIdx.x, warp = tid >> 5, lane = tid & 31;
    const int g2 = lane >> 2, t4 = lane & 3;
    const int q0 = qb * BQ;
    const size_t vtbase = (size_t)(b * NHEAD + h) * HDIM * SEQ;

    // Q tile: 128x64 fp16, scaled by 0.125*log2e
    {
        const __half2 sc2 = __float2half2_rn(SCALE_L2E);
        #pragma unroll
        for (int i = 0; i < 4; i++) {
            int idx = tid + i * 256;              // 1024 chunks of 8 halfs
            int r = idx >> 3, p = idx & 7;
            const __half2* src = reinterpret_cast<const __half2*>(
                qkvh + (size_t)(b * SEQ + q0 + r) * 2048 + h * 64 + p * 8);
            __half2* dst = reinterpret_cast<__half2*>(Qs + r * QH_S + p * 8);
            dst[0] = __hmul2(src[0], sc2);
            dst[1] = __hmul2(src[1], sc2);
            dst[2] = __hmul2(src[2], sc2);
            dst[3] = __hmul2(src[3], sc2);
        }
    }

    const int r0l = warp * 16 + g2;
    const int grow0 = q0 + r0l, grow1 = grow0 + 8;
    float m0 = -1e30f, m1 = -1e30f, l0 = 0.f, l1 = 0.f;
    float o[8][4];
    #pragma unroll
    for (int nf = 0; nf < 8; nf++)
        #pragma unroll
        for (int i = 0; i < 4; i++) o[nf][i] = 0.f;

    const int nkv = 2 * qb + 2;

    // prefetch KV tile 0 (stage 0): K rows [kv][hd], Vt rows [d][kv]
    #pragma unroll
    for (int i = 0; i < 2; i++) {
        int idx = tid + i * 256;
        int r = idx >> 3, p = idx & 7;
        CP16(smem_u32(Ks + r * KH_S + p * 8),
             qkvh + (size_t)(b * SEQ + r) * 2048 + 1024 + h * 64 + p * 8);
    }
    #pragma unroll
    for (int i = 0; i < 2; i++) {
        int idx = tid + i * 256;
        int r = idx >> 3, p = idx & 7;
        CP16(smem_u32(Vst + r * VH_S + p * 8), vt + vtbase + (size_t)r * SEQ + p * 8);
    }
    CP_COMMIT();

    for (int t = 0; t < nkv; t++) {
        CP_WAIT0();
        __syncthreads();

        if (t + 1 < nkv) {
            const int kv1 = (t + 1) * BKV;
            __half* Kd = Ks + ((t + 1) & 1) * 64 * KH_S;
            __half* Vd = Vst + ((t + 1) & 1) * 64 * VH_S;
            #pragma unroll
            for (int i = 0; i < 2; i++) {
                int idx = tid + i * 256;
                int r = idx >> 3, p = idx & 7;
                CP16(smem_u32(Kd + r * KH_S + p * 8),
                     qkvh + (size_t)(b * SEQ + kv1 + r) * 2048 + 1024 + h * 64 + p * 8);
            }
            #pragma unroll
            for (int i = 0; i < 2; i++) {
                int idx = tid + i * 256;
                int r = idx >> 3, p = idx & 7;
                CP16(smem_u32(Vd + r * VH_S + p * 8),
                     vt + vtbase + (size_t)r * SEQ + kv1 + p * 8);
            }
            CP_COMMIT();
        }

        const __half* Kc = Ks + (t & 1) * 64 * KH_S;
        const __half* Vc = Vst + (t & 1) * 64 * VH_S;

        // ---- S = Qs @ K^T (log2 units), 4 x k16 ----
        float s[8][4];
        #pragma unroll
        for (int nf = 0; nf < 8; nf++)
            #pragma unroll
            for (int i = 0; i < 4; i++) s[nf][i] = 0.f;

        #pragma unroll
        for (int ks = 0; ks < 4; ks++) {
            const int k = ks * 16;
            uint32_t a0 = ldh2(Qs + r0l * QH_S + k + 2 * t4);
            uint32_t a1 = ldh2(Qs + (r0l + 8) * QH_S + k + 2 * t4);
            uint32_t a2 = ldh2(Qs + r0l * QH_S + k + 2 * t4 + 8);
            uint32_t a3 = ldh2(Qs + (r0l + 8) * QH_S + k + 2 * t4 + 8);
            #pragma unroll
            for (int nf = 0; nf < 8; nf++) {
                int cc = nf * 8 + g2;
                uint32_t b0 = ldh2(Kc + cc * KH_S + k + 2 * t4);
                uint32_t b1 = ldh2(Kc + cc * KH_S + k + 2 * t4 + 8);
                mma16(s[nf], a0, a1, a2, a3, b0, b1);
            }
        }

        // ---- mask + quad row max ----
        const bool nm = (t >= nkv - 2);
        float mx0 = -1e30f, mx1 = -1e30f;
        #pragma unroll
        for (int nf = 0; nf < 8; nf++) {
            #pragma unroll
            for (int j = 0; j < 2; j++) {
                int gc = t * BKV + nf * 8 + t4 * 2 + j;
                if (nm && gc > grow0) s[nf][j]     = -1e30f;
                if (nm && gc > grow1) s[nf][2 + j] = -1e30f;
                mx0 = fmaxf(mx0, s[nf][j]);
                mx1 = fmaxf(mx1, s[nf][2 + j]);
            }
        }
        mx0 = fmaxf(mx0, __shfl_xor_sync(0xffffffffu, mx0, 1));
        mx0 = fmaxf(mx0, __shfl_xor_sync(0xffffffffu, mx0, 2));
        mx1 = fmaxf(mx1, __shfl_xor_sync(0xffffffffu, mx1, 1));
        mx1 = fmaxf(mx1, __shfl_xor_sync(0xffffffffu, mx1, 2));

        const float mn0 = fmaxf(m0, mx0);
        const float mn1 = fmaxf(m1, mx1);
        const float a0s = ex2(m0 - mn0);
        const float a1s = ex2(m1 - mn1);

        // ---- P = ex2 in f16x2 (one MUFU op per 2 elements) ----
        float ps0 = 0.f, ps1 = 0.f;
        #pragma unroll
        for (int nf = 0; nf < 8; nf++) {
            __half2 e0 = h2ex2(__floats2half2_rn(s[nf][0] - mn0, s[nf][1] - mn0));
            __half2 e1 = h2ex2(__floats2half2_rn(s[nf][2] - mn1, s[nf][3] - mn1));
            int cc = nf * 8 + t4 * 2;
            *reinterpret_cast<__half2*>(Ps + r0l * PH_S + cc)       = e0;
            *reinterpret_cast<__half2*>(Ps + (r0l + 8) * PH_S + cc) = e1;
            float2 f0 = __half22float2(e0);
            float2 f1 = __half22float2(e1);
            ps0 += f0.x + f0.y;
            ps1 += f1.x + f1.y;
        }
        ps0 += __shfl_xor_sync(0xffffffffu, ps0, 1);
        ps0 += __shfl_xor_sync(0xffffffffu, ps0, 2);
        ps1 += __shfl_xor_sync(0xffffffffu, ps1, 1);
        ps1 += __shfl_xor_sync(0xffffffffu, ps1, 2);
        l0 = l0 * a0s + ps0;
        l1 = l1 * a1s + ps1;
        m0 = mn0; m1 = mn1;

        #pragma unroll
        for (int nf = 0; nf < 8; nf++) {
            o[nf][0] *= a0s; o[nf][1] *= a0s;
            o[nf][2] *= a1s; o[nf][3] *= a1s;
        }
        __syncwarp();   // P rows are warp-private

        // ---- O += P @ V ----
        #pragma unroll
        for (int ks = 0; ks < 4; ks++) {
            const int k = ks * 16;
            uint32_t a0 = ldh2(Ps + r0l * PH_S + k + 2 * t4);
            uint32_t a1 = ldh2(Ps + (r0l + 8) * PH_S + k + 2 * t4);
            uint32_t a2 = ldh2(Ps + r0l * PH_S + k + 2 * t4 + 8);
            uint32_t a3 = ldh2(Ps + (r0l + 8) * PH_S + k + 2 * t4 + 8);
            #pragma unroll
            for (int nf = 0; nf < 8; nf++) {
                int cc = nf * 8 + g2;
                uint32_t b0 = ldh2(Vc + cc * VH_S + k + 2 * t4);
                uint32_t b1 = ldh2(Vc + cc * VH_S + k + 2 * t4 + 8);
                mma16(o[nf], a0, a1, a2, a3, b0, b1);
            }
        }
    }

    const float inv0 = 1.f / l0, inv1 = 1.f / l1;
    #pragma unroll
    for (int nf = 0; nf < 8; nf++) {
        int cc = nf * 8 + t4 * 2;
        __half* p0 = attn_out + (size_t)(b * SEQ + grow0) * HID + h * 64 + cc;
        __half* p1 = attn_out + (size_t)(b * SEQ + grow1) * HID + h * 64 + cc;
        *reinterpret_cast<__half2*>(p0) =
            __float22half2_rn(make_float2(o[nf][0] * inv0, o[nf][1] * inv0));
        *reinterpret_cast<__half2*>(p1) =
            __float22half2_rn(make_float2(o[nf][2] * inv1, o[nf][3] * inv1));
    }
}

// ---------------------------------------------------------------------------
extern "C" void kernel_launch(void* const* d_in, const int* in_sizes, int n_in,
                              void* d_out, int out_size)
{
    const float* x     = (const float*)d_in[0];
    const float* w_qkv = (const float*)d_in[1];
    const float* b_qkv = (const float*)d_in[2];
    const float* w_out = (const float*)d_in[3];
    const float* b_out = (const float*)d_in[4];
    float* out = (float*)d_out;

    __half *xh, *w1t, *w2t, *qkvh, *vt, *attnh;
    cudaGetSymbolAddress((void**)&xh,    g_xh);
    cudaGetSymbolAddress((void**)&w1t,   g_w1t);
    cudaGetSymbolAddress((void**)&w2t,   g_w2t);
    cudaGetSymbolAddress((void**)&qkvh,  g_qkvh);
    cudaGetSymbolAddress((void**)&vt,    g_vt);
    cudaGetSymbolAddress((void**)&attnh, g_attnh);

    cudaFuncSetAttribute(gemm_h,  cudaFuncAttributeMaxDynamicSharedMemorySize, GEMM_SMEM);
    cudaFuncSetAttribute(flash_h, cudaFuncAttributeMaxDynamicSharedMemorySize, FLASH_SMEM);

    // 0) prepasses: x -> fp16; weights -> fp16 transposed [N][K]
    conv_h_kernel<<<(NTOK * HID / 4 + 255) / 256, 256>>>(x, xh, NTOK * HID / 4);
    transpose_h_kernel<<<dim3(3 * HID / 32, HID / 32), 256>>>(w_qkv, w1t, HID, 3 * HID);
    transpose_h_kernel<<<dim3(HID / 32, HID / 32), 256>>>(w_out, w2t, HID, HID);

    // 1) qkv = x @ w_qkv + b_qkv  (fp16 out; V transposed)
    dim3 g1(3 * HID / 256, NTOK / 128);
    gemm_h<<<g1, 256, GEMM_SMEM>>>(xh, w1t, b_qkv, nullptr, qkvh, vt,
                                   NTOK, 3 * HID, HID, 1);

    // 2) causal flash attention (fp16, f16x2 exp)
    dim3 g2(SEQ / BQ, NHEAD, BATCH);
    flash_h<<<g2, 256, FLASH_SMEM>>>(qkvh, vt, attnh);

    // 3) out = attn @ w_out + b_out  (fp32 out)
    dim3 g3(HID / 256, NTOK / 128);
    gemm_h<<<g3, 256, GEMM_SMEM>>>(attnh, w2t, b_out, out, nullptr, nullptr,
                                   NTOK, HID, HID, 0);
}

// round 16
// speedup vs baseline: 1.0793x; 1.0793x over previous
#include <cuda_runtime.h>
#include <cuda_fp16.h>
#include <cstdint>

#define BATCH 2
#define SEQ   2048
#define HID   1024
#define NHEAD 16
#define HDIM  64
#define NTOK  (BATCH*SEQ)

// ---------------- device scratch (allocation-free rule) ----------------
__device__ __half g_xh   [NTOK * HID];          // x fp16 [M][K]
__device__ __half g_w1t  [3 * HID * HID];       // w_qkv^T fp16 [N=3072][K=1024]
__device__ __half g_w2t  [HID * HID];           // w_out^T fp16 [N=1024][K=1024]
__device__ __half g_qkvh [NTOK * 2 * HID];      // Q,K halves fp16 [tok][2048]
__device__ __half g_vt   [BATCH * NHEAD * HDIM * SEQ];  // V^T fp16 [(b,h,d)][s]
__device__ __half g_attnh[NTOK * HID];          // attn out fp16 [tok][1024]

// ---------------------------------------------------------------------------
__device__ __forceinline__ float ex2(float x) {
    float y;
    asm("ex2.approx.ftz.f32 %0, %1;" : "=f"(y) : "f"(x));
    return y;
}
__device__ __forceinline__ __half2 h2ex2(__half2 x) {
    uint32_t xi = *reinterpret_cast<uint32_t*>(&x);
    uint32_t yi;
    asm("ex2.approx.f16x2 %0, %1;" : "=r"(yi) : "r"(xi));
    return *reinterpret_cast<__half2*>(&yi);
}
__device__ __forceinline__ uint32_t h2bits(__half2 x) {
    return *reinterpret_cast<uint32_t*>(&x);
}
__device__ __forceinline__ uint32_t smem_u32(const void* p) {
    return (uint32_t)__cvta_generic_to_shared(p);
}
#define CP16(dst_u32, src_ptr) \
    asm volatile("cp.async.ca.shared.global [%0], [%1], 16;" :: "r"(dst_u32), "l"(src_ptr))
#define CP_COMMIT() asm volatile("cp.async.commit_group;")
#define CP_WAIT0()  asm volatile("cp.async.wait_group 0;")

#define LDSM4(d0, d1, d2, d3, addr) \
    asm volatile("ldmatrix.sync.aligned.m8n8.x4.shared.b16 {%0,%1,%2,%3}, [%4];" \
        : "=r"(d0), "=r"(d1), "=r"(d2), "=r"(d3) : "r"(addr))

// fp16 mma: D(f32) = A(f16) * B(f16) + D, m16n8k16
__device__ __forceinline__ void mma16(float* c,
                                      uint32_t a0, uint32_t a1, uint32_t a2, uint32_t a3,
                                      uint32_t b0, uint32_t b1) {
    asm volatile(
        "mma.sync.aligned.m16n8k16.row.col.f32.f16.f16.f32 "
        "{%0,%1,%2,%3}, {%4,%5,%6,%7}, {%8,%9}, {%0,%1,%2,%3};"
        : "+f"(c[0]), "+f"(c[1]), "+f"(c[2]), "+f"(c[3])
        : "r"(a0), "r"(a1), "r"(a2), "r"(a3), "r"(b0), "r"(b1));
}

// ---------------------------------------------------------------------------
// prepass 1: x fp32 -> fp16
// ---------------------------------------------------------------------------
__global__ void conv_h_kernel(const float* __restrict__ in, __half* __restrict__ out, int n4)
{
    int i = blockIdx.x * blockDim.x + threadIdx.x;
    if (i >= n4) return;
    float4 v = reinterpret_cast<const float4*>(in)[i];
    __half2 h0 = __float22half2_rn(make_float2(v.x, v.y));
    __half2 h1 = __float22half2_rn(make_float2(v.z, v.w));
    reinterpret_cast<uint2*>(out)[i] =
        make_uint2(*reinterpret_cast<uint32_t*>(&h0), *reinterpret_cast<uint32_t*>(&h1));
}

// prepass 2: w fp32 [K][N] -> fp16 [N][K] (transpose)
__global__ void transpose_h_kernel(const float* __restrict__ in, __half* __restrict__ out,
                                   int K, int N)
{
    __shared__ float t[32][33];
    const int n0 = blockIdx.x * 32, k0 = blockIdx.y * 32;
    const int tx = threadIdx.x & 31, ty = threadIdx.x >> 5;   // 32 x 8
    #pragma unroll
    for (int i = 0; i < 4; i++)
        t[ty + i * 8][tx] = in[(size_t)(k0 + ty + i * 8) * N + n0 + tx];
    __syncthreads();
    #pragma unroll
    for (int i = 0; i < 4; i++)
        out[(size_t)(n0 + ty + i * 8) * K + k0 + tx] = __float2half_rn(t[tx][ty + i * 8]);
}

// ---------------------------------------------------------------------------
// FP16 GEMM with ldmatrix fragment loads. CTA tile 128x256, BK=64, 256 thr
// (8 warps 2x4, 64x64 warp tiles), 2-stage cp.async, 1 barrier/iter.
// ---------------------------------------------------------------------------
#define GAH 72
#define GBH 72
#define STAGE_H (128*GAH + 256*GBH)            // halfs per stage = 27648
#define GEMM_SMEM (2 * STAGE_H * 2)            // 110592 B

__global__ __launch_bounds__(256, 1) void gemm_h(
    const __half* __restrict__ A, const __half* __restrict__ Bt,
    const float* __restrict__ bias,
    float* __restrict__ Cf, __half* __restrict__ Ch, __half* __restrict__ vt,
    int M, int N, int K, int mode)
{
    extern __shared__ __half smh[];

    const int tid  = threadIdx.x;
    const int warp = tid >> 5, lane = tid & 31;
    const int wm = warp >> 2, wn = warp & 3;   // 2 x 4 warp grid -> 64x64 tiles
    const int g2 = lane >> 2, t4 = lane & 3;
    const int quad = lane >> 3, tin = lane & 7;     // ldmatrix addressing
    const int lrow = (quad & 1) * 8 + tin;          // row within 16-row group
    const int lcol = (quad >> 1) * 8;               // col offset 0/8
    const int cRow = blockIdx.y, cCol = blockIdx.x;

    const __half* Ab = A + (size_t)cRow * 128 * K;
    const __half* Bb = Bt + (size_t)cCol * 256 * K;

    float c[4][8][4];
    #pragma unroll
    for (int mf = 0; mf < 4; mf++)
        #pragma unroll
        for (int nf = 0; nf < 8; nf++)
            #pragma unroll
            for (int i = 0; i < 4; i++) c[mf][nf][i] = 0.f;

    const int nk = K >> 6;    // BK=64

    // prologue: prefetch stage 0
    {
        __half* Ad = smh;
        __half* Bd = smh + 128 * GAH;
        #pragma unroll
        for (int i = 0; i < 4; i++) {
            int idx = tid + i * 256;
            int r = idx >> 3, p = idx & 7;
            CP16(smem_u32(Ad + r * GAH + p * 8), Ab + (size_t)r * K + p * 8);
        }
        #pragma unroll
        for (int i = 0; i < 8; i++) {
            int idx = tid + i * 256;
            int r = idx >> 3, p = idx & 7;
            CP16(smem_u32(Bd + r * GBH + p * 8), Bb + (size_t)r * K + p * 8);
        }
        CP_COMMIT();
    }

    for (int it = 0; it < nk; it++) {
        CP_WAIT0();
        __syncthreads();

        if (it + 1 < nk) {
            const int k0 = (it + 1) << 6;
            __half* Ad = smh + ((it + 1) & 1) * STAGE_H;
            __half* Bd = Ad + 128 * GAH;
            #pragma unroll
            for (int i = 0; i < 4; i++) {
                int idx = tid + i * 256;
                int r = idx >> 3, p = idx & 7;
                CP16(smem_u32(Ad + r * GAH + p * 8), Ab + (size_t)r * K + k0 + p * 8);
            }
            #pragma unroll
            for (int i = 0; i < 8; i++) {
                int idx = tid + i * 256;
                int r = idx >> 3, p = idx & 7;
                CP16(smem_u32(Bd + r * GBH + p * 8), Bb + (size_t)r * K + k0 + p * 8);
            }
            CP_COMMIT();
        }

        const __half* Ac = smh + (it & 1) * STAGE_H;
        const __half* Bc = Ac + 128 * GAH;

        #pragma unroll
        for (int ks = 0; ks < 4; ks++) {          // 4 x k16 = BK 64
            const int k = ks * 16;
            uint32_t a[4][4], b[8][2];
            #pragma unroll
            for (int mf = 0; mf < 4; mf++) {
                uint32_t addr = smem_u32(Ac + (wm * 64 + mf * 16 + lrow) * GAH + k + lcol);
                LDSM4(a[mf][0], a[mf][1], a[mf][2], a[mf][3], addr);
            }
            #pragma unroll
            for (int nfp = 0; nfp < 4; nfp++) {
                uint32_t addr = smem_u32(Bc + (wn * 64 + nfp * 16 + lrow) * GBH + k + lcol);
                LDSM4(b[2 * nfp][0], b[2 * nfp + 1][0], b[2 * nfp][1], b[2 * nfp + 1][1], addr);
            }
            #pragma unroll
            for (int mf = 0; mf < 4; mf++)
                #pragma unroll
                for (int nf = 0; nf < 8; nf++)
                    mma16(c[mf][nf], a[mf][0], a[mf][1], a[mf][2], a[mf][3],
                          b[nf][0], b[nf][1]);
        }
    }

    // epilogue
    #pragma unroll
    for (int nf = 0; nf < 8; nf++) {
        int col = cCol * 256 + wn * 64 + nf * 8 + t4 * 2;
        float b0 = bias[col], b1 = bias[col + 1];
        #pragma unroll
        for (int mf = 0; mf < 4; mf++) {
            int r0 = cRow * 128 + wm * 64 + mf * 16 + g2;
            float v00 = c[mf][nf][0] + b0, v01 = c[mf][nf][1] + b1;
            float v10 = c[mf][nf][2] + b0, v11 = c[mf][nf][3] + b1;
            if (mode == 0) {
                *reinterpret_cast<float2*>(Cf + (size_t)r0 * N + col)       = make_float2(v00, v01);
                *reinterpret_cast<float2*>(Cf + (size_t)(r0 + 8) * N + col) = make_float2(v10, v11);
            } else {
                if (col < 2048) {     // Q,K -> qkvh fp16 [tok][2048]
                    __half2 h0 = __float22half2_rn(make_float2(v00, v01));
                    __half2 h1 = __float22half2_rn(make_float2(v10, v11));
                    *reinterpret_cast<__half2*>(Ch + (size_t)r0 * 2048 + col)       = h0;
                    *reinterpret_cast<__half2*>(Ch + (size_t)(r0 + 8) * 2048 + col) = h1;
                } else {              // V -> vt transposed [(b,h,d)][s]
                    int hh = (col - 2048) >> 6, d = (col - 2048) & 63;
                    int b0i = r0 >> 11, s0 = r0 & 2047;
                    int b1i = (r0 + 8) >> 11, s1 = (r0 + 8) & 2047;
                    size_t base0 = ((size_t)(b0i * NHEAD + hh) * HDIM + d) * SEQ;
                    size_t base1 = ((size_t)(b1i * NHEAD + hh) * HDIM + d) * SEQ;
                    vt[base0 + s0]       = __float2half_rn(v00);
                    vt[base0 + SEQ + s0] = __float2half_rn(v01);
                    vt[base1 + s1]       = __float2half_rn(v10);
                    vt[base1 + SEQ + s1] = __float2half_rn(v11);
                }
            }
        }
    }
}

// ---------------------------------------------------------------------------
// FP16 causal flash attention: BQ=128, BKV=64, 256 threads (8 warps).
// Q fragments preloaded once (registers); K/V via ldmatrix; P lives only in
// registers (exp output IS the PV A-fragment). No P smem, no syncwarp.
// ---------------------------------------------------------------------------
#define BQ  128
#define BKV 64
#define QH_S 72
#define KH_S 72
#define VH_S 72
#define SCALE_L2E 0.18033688011112042f   // 0.125 * log2(e)
#define FLASH_SMEM ((128*QH_S + 2*64*KH_S + 2*64*VH_S) * 2)  // 55296 B

__global__ __launch_bounds__(256, 1) void flash_h(
    const __half* __restrict__ qkvh, const __half* __restrict__ vt,
    __half* __restrict__ attn_out)
{
    extern __shared__ __half smh[];
    __half* Qs  = smh;                      // [128][72]
    __half* Ks  = Qs + 128 * QH_S;          // [2][64][72]
    __half* Vst = Ks + 2 * 64 * KH_S;       // [2][64][72]  (Vst[d][kv])

    const int qb = gridDim.x - 1 - blockIdx.x;   // heavy blocks first
    const int h = blockIdx.y, b = blockIdx.z;
    const int tid = threadIdx.x, warp = tid >> 5, lane = tid & 31;
    const int g2 = lane >> 2, t4 = lane & 3;
    const int quad = lane >> 3, tin = lane & 7;
    const int lrow = (quad & 1) * 8 + tin;
    const int lcol = (quad >> 1) * 8;
    const int q0 = qb * BQ;
    const size_t vtbase = (size_t)(b * NHEAD + h) * HDIM * SEQ;

    // Q tile: 128x64 fp16, scaled by 0.125*log2e
    {
        const __half2 sc2 = __float2half2_rn(SCALE_L2E);
        #pragma unroll
        for (int i = 0; i < 4; i++) {
            int idx = tid + i * 256;
            int r = idx >> 3, p = idx & 7;
            const __half2* src = reinterpret_cast<const __half2*>(
                qkvh + (size_t)(b * SEQ + q0 + r) * 2048 + h * 64 + p * 8);
            __half2* dst = reinterpret_cast<__half2*>(Qs + r * QH_S + p * 8);
            dst[0] = __hmul2(src[0], sc2);
            dst[1] = __hmul2(src[1], sc2);
            dst[2] = __hmul2(src[2], sc2);
            dst[3] = __hmul2(src[3], sc2);
        }
    }

    // prefetch KV tile 0 while Q settles
    #pragma unroll
    for (int i = 0; i < 2; i++) {
        int idx = tid + i * 256;
        int r = idx >> 3, p = idx & 7;
        CP16(smem_u32(Ks + r * KH_S + p * 8),
             qkvh + (size_t)(b * SEQ + r) * 2048 + 1024 + h * 64 + p * 8);
    }
    #pragma unroll
    for (int i = 0; i < 2; i++) {
        int idx = tid + i * 256;
        int r = idx >> 3, p = idx & 7;
        CP16(smem_u32(Vst + r * VH_S + p * 8), vt + vtbase + (size_t)r * SEQ + p * 8);
    }
    CP_COMMIT();

    __syncthreads();   // Q smem complete -> fragment preload
    uint32_t qa[4][4];
    #pragma unroll
    for (int ks = 0; ks < 4; ks++) {
        uint32_t addr = smem_u32(Qs + (warp * 16 + lrow) * QH_S + ks * 16 + lcol);
        LDSM4(qa[ks][0], qa[ks][1], qa[ks][2], qa[ks][3], addr);
    }

    const int r0l = warp * 16 + g2;
    const int grow0 = q0 + r0l, grow1 = grow0 + 8;
    float m0 = -1e30f, m1 = -1e30f, l0 = 0.f, l1 = 0.f;
    float o[8][4];
    #pragma unroll
    for (int nf = 0; nf < 8; nf++)
        #pragma unroll
        for (int i = 0; i < 4; i++) o[nf][i] = 0.f;

    const int nkv = 2 * qb + 2;

    for (int t = 0; t < nkv; t++) {
        CP_WAIT0();
        __syncthreads();

        if (t + 1 < nkv) {
            const int kv1 = (t + 1) * BKV;
            __half* Kd = Ks + ((t + 1) & 1) * 64 * KH_S;
            __half* Vd = Vst + ((t + 1) & 1) * 64 * VH_S;
            #pragma unroll
            for (int i = 0; i < 2; i++) {
                int idx = tid + i * 256;
                int r = idx >> 3, p = idx & 7;
                CP16(smem_u32(Kd + r * KH_S + p * 8),
                     qkvh + (size_t)(b * SEQ + kv1 + r) * 2048 + 1024 + h * 64 + p * 8);
            }
            #pragma unroll
            for (int i = 0; i < 2; i++) {
                int idx = tid + i * 256;
                int r = idx >> 3, p = idx & 7;
                CP16(smem_u32(Vd + r * VH_S + p * 8),
                     vt + vtbase + (size_t)r * SEQ + kv1 + p * 8);
            }
            CP_COMMIT();
        }

        const __half* Kc = Ks + (t & 1) * 64 * KH_S;
        const __half* Vc = Vst + (t & 1) * 64 * VH_S;

        // ---- S = Q @ K^T (log2 units) ----
        float s[8][4];
        #pragma unroll
        for (int nf = 0; nf < 8; nf++)
            #pragma unroll
            for (int i = 0; i < 4; i++) s[nf][i] = 0.f;

        #pragma unroll
        for (int ks = 0; ks < 4; ks++) {
            const int k = ks * 16;
            uint32_t kb[8][2];
            #pragma unroll
            for (int nfp = 0; nfp < 4; nfp++) {
                uint32_t addr = smem_u32(Kc + (nfp * 16 + lrow) * KH_S + k + lcol);
                LDSM4(kb[2 * nfp][0], kb[2 * nfp + 1][0],
                      kb[2 * nfp][1], kb[2 * nfp + 1][1], addr);
            }
            #pragma unroll
            for (int nf = 0; nf < 8; nf++)
                mma16(s[nf], qa[ks][0], qa[ks][1], qa[ks][2], qa[ks][3],
                      kb[nf][0], kb[nf][1]);
        }

        // ---- mask + quad row max ----
        const bool nm = (t >= nkv - 2);
        float mx0 = -1e30f, mx1 = -1e30f;
        #pragma unroll
        for (int nf = 0; nf < 8; nf++) {
            #pragma unroll
            for (int j = 0; j < 2; j++) {
                int gc = t * BKV + nf * 8 + t4 * 2 + j;
                if (nm && gc > grow0) s[nf][j]     = -1e30f;
                if (nm && gc > grow1) s[nf][2 + j] = -1e30f;
                mx0 = fmaxf(mx0, s[nf][j]);
                mx1 = fmaxf(mx1, s[nf][2 + j]);
            }
        }
        mx0 = fmaxf(mx0, __shfl_xor_sync(0xffffffffu, mx0, 1));
        mx0 = fmaxf(mx0, __shfl_xor_sync(0xffffffffu, mx0, 2));
        mx1 = fmaxf(mx1, __shfl_xor_sync(0xffffffffu, mx1, 1));
        mx1 = fmaxf(mx1, __shfl_xor_sync(0xffffffffu, mx1, 2));

        const float mn0 = fmaxf(m0, mx0);
        const float mn1 = fmaxf(m1, mx1);
        const float a0s = ex2(m0 - mn0);
        const float a1s = ex2(m1 - mn1);

        // ---- P = ex2.f16x2, straight into PV A-fragments ----
        uint32_t pf0[8], pf1[8];
        float ps0 = 0.f, ps1 = 0.f;
        #pragma unroll
        for (int nf = 0; nf < 8; nf++) {
            __half2 e0 = h2ex2(__floats2half2_rn(s[nf][0] - mn0, s[nf][1] - mn0));
            __half2 e1 = h2ex2(__floats2half2_rn(s[nf][2] - mn1, s[nf][3] - mn1));
            pf0[nf] = h2bits(e0);
            pf1[nf] = h2bits(e1);
            float2 f0 = __half22float2(e0);
            float2 f1 = __half22float2(e1);
            ps0 += f0.x + f0.y;
            ps1 += f1.x + f1.y;
        }
        ps0 += __shfl_xor_sync(0xffffffffu, ps0, 1);
        ps0 += __shfl_xor_sync(0xffffffffu, ps0, 2);
        ps1 += __shfl_xor_sync(0xffffffffu, ps1, 1);
        ps1 += __shfl_xor_sync(0xffffffffu, ps1, 2);
        l0 = l0 * a0s + ps0;
        l1 = l1 * a1s + ps1;
        m0 = mn0; m1 = mn1;

        #pragma unroll
        for (int nf = 0; nf < 8; nf++) {
            o[nf][0] *= a0s; o[nf][1] *= a0s;
            o[nf][2] *= a1s; o[nf][3] *= a1s;
        }

        // ---- O += P @ V : A = pf registers, B = Vst via ldmatrix ----
        #pragma unroll
        for (int ks = 0; ks < 4; ks++) {
            const int k = ks * 16;
            uint32_t vb[8][2];
            #pragma unroll
            for (int nfp = 0; nfp < 4; nfp++) {
                uint32_t addr = smem_u32(Vc + (nfp * 16 + lrow) * VH_S + k + lcol);
                LDSM4(vb[2 * nfp][0], vb[2 * nfp + 1][0],
                      vb[2 * nfp][1], vb[2 * nfp + 1][1], addr);
            }
            #pragma unroll
            for (int nf = 0; nf < 8; nf++)
                mma16(o[nf], pf0[2 * ks], pf1[2 * ks], pf0[2 * ks + 1], pf1[2 * ks + 1],
                      vb[nf][0], vb[nf][1]);
        }
    }

    const float inv0 = 1.f / l0, inv1 = 1.f / l1;
    #pragma unroll
    for (int nf = 0; nf < 8; nf++) {
        int cc = nf * 8 + t4 * 2;
        __half* p0 = attn_out + (size_t)(b * SEQ + grow0) * HID + h * 64 + cc;
        __half* p1 = attn_out + (size_t)(b * SEQ + grow1) * HID + h * 64 + cc;
        *reinterpret_cast<__half2*>(p0) =
            __float22half2_rn(make_float2(o[nf][0] * inv0, o[nf][1] * inv0));
        *reinterpret_cast<__half2*>(p1) =
            __float22half2_rn(make_float2(o[nf][2] * inv1, o[nf][3] * inv1));
    }
}

// ---------------------------------------------------------------------------
extern "C" void kernel_launch(void* const* d_in, const int* in_sizes, int n_in,
                              void* d_out, int out_size)
{
    const float* x     = (const float*)d_in[0];
    const float* w_qkv = (const float*)d_in[1];
    const float* b_qkv = (const float*)d_in[2];
    const float* w_out = (const float*)d_in[3];
    const float* b_out = (const float*)d_in[4];
    float* out = (float*)d_out;

    __half *xh, *w1t, *w2t, *qkvh, *vt, *attnh;
    cudaGetSymbolAddress((void**)&xh,    g_xh);
    cudaGetSymbolAddress((void**)&w1t,   g_w1t);
    cudaGetSymbolAddress((void**)&w2t,   g_w2t);
    cudaGetSymbolAddress((void**)&qkvh,  g_qkvh);
    cudaGetSymbolAddress((void**)&vt,    g_vt);
    cudaGetSymbolAddress((void**)&attnh, g_attnh);

    cudaFuncSetAttribute(gemm_h,  cudaFuncAttributeMaxDynamicSharedMemorySize, GEMM_SMEM);
    cudaFuncSetAttribute(flash_h, cudaFuncAttributeMaxDynamicSharedMemorySize, FLASH_SMEM);

    // 0) prepasses: x -> fp16; weights -> fp16 transposed [N][K]
    conv_h_kernel<<<(NTOK * HID / 4 + 255) / 256, 256>>>(x, xh, NTOK * HID / 4);
    transpose_h_kernel<<<dim3(3 * HID / 32, HID / 32), 256>>>(w_qkv, w1t, HID, 3 * HID);
    transpose_h_kernel<<<dim3(HID / 32, HID / 32), 256>>>(w_out, w2t, HID, HID);

    // 1) qkv = x @ w_qkv + b_qkv  (fp16 out; V transposed)
    dim3 g1(3 * HID / 256, NTOK / 128);
    gemm_h<<<g1, 256, GEMM_SMEM>>>(xh, w1t, b_qkv, nullptr, qkvh, vt,
                                   NTOK, 3 * HID, HID, 1);

    // 2) causal flash attention
    dim3 g2(SEQ / BQ, NHEAD, BATCH);
    flash_h<<<g2, 256, FLASH_SMEM>>>(qkvh, vt, attnh);

    // 3) out = attn @ w_out + b_out  (fp32 out)
    dim3 g3(HID / 256, NTOK / 128);
    gemm_h<<<g3, 256, GEMM_SMEM>>>(attnh, w2t, b_out, out, nullptr, nullptr,
                                   NTOK, HID, HID, 0);
}

// round 17
// speedup vs baseline: 1.1241x; 1.0415x over previous
#include <cuda_runtime.h>
#include <cuda_fp16.h>
#include <cstdint>

#define BATCH 2
#define SEQ   2048
#define HID   1024
#define NHEAD 16
#define HDIM  64
#define NTOK  (BATCH*SEQ)

// ---------------- device scratch (allocation-free rule) ----------------
__device__ __half g_xh   [NTOK * HID];          // x fp16 [M][K]
__device__ __half g_w1t  [3 * HID * HID];       // w_qkv^T fp16 [N=3072][K=1024]
__device__ __half g_w2t  [HID * HID];           // w_out^T fp16 [N=1024][K=1024]
__device__ __half g_qkvh [NTOK * 2 * HID];      // Q,K halves fp16 [tok][2048]
__device__ __half g_vt   [BATCH * NHEAD * HDIM * SEQ];  // V^T fp16 [(b,h,d)][s]
__device__ __half g_attnh[NTOK * HID];          // attn out fp16 [tok][1024]

// ---------------------------------------------------------------------------
__device__ __forceinline__ float ex2(float x) {
    float y;
    asm("ex2.approx.ftz.f32 %0, %1;" : "=f"(y) : "f"(x));
    return y;
}
__device__ __forceinline__ __half2 h2ex2(__half2 x) {
    uint32_t xi = *reinterpret_cast<uint32_t*>(&x);
    uint32_t yi;
    asm("ex2.approx.f16x2 %0, %1;" : "=r"(yi) : "r"(xi));
    return *reinterpret_cast<__half2*>(&yi);
}
__device__ __forceinline__ uint32_t h2bits(__half2 x) {
    return *reinterpret_cast<uint32_t*>(&x);
}
__device__ __forceinline__ uint32_t smem_u32(const void* p) {
    return (uint32_t)__cvta_generic_to_shared(p);
}
#define CP16(dst_u32, src_ptr) \
    asm volatile("cp.async.ca.shared.global [%0], [%1], 16;" :: "r"(dst_u32), "l"(src_ptr))
#define CP_COMMIT() asm volatile("cp.async.commit_group;")
#define CP_WAIT0()  asm volatile("cp.async.wait_group 0;")

#define LDSM4(d0, d1, d2, d3, addr) \
    asm volatile("ldmatrix.sync.aligned.m8n8.x4.shared.b16 {%0,%1,%2,%3}, [%4];" \
        : "=r"(d0), "=r"(d1), "=r"(d2), "=r"(d3) : "r"(addr))

// fp16 mma: D(f32) = A(f16) * B(f16) + D, m16n8k16
__device__ __forceinline__ void mma16(float* c,
                                      uint32_t a0, uint32_t a1, uint32_t a2, uint32_t a3,
                                      uint32_t b0, uint32_t b1) {
    asm volatile(
        "mma.sync.aligned.m16n8k16.row.col.f32.f16.f16.f32 "
        "{%0,%1,%2,%3}, {%4,%5,%6,%7}, {%8,%9}, {%0,%1,%2,%3};"
        : "+f"(c[0]), "+f"(c[1]), "+f"(c[2]), "+f"(c[3])
        : "r"(a0), "r"(a1), "r"(a2), "r"(a3), "r"(b0), "r"(b1));
}

// ---------------------------------------------------------------------------
// merged prepass: one launch.
//  blocks [0, XB)            : x fp32 -> fp16 (vectorized copy)
//  blocks [XB, XB+W1B)       : w_qkv [K][3072] -> w1t [3072][K] fp16
//  blocks [XB+W1B, +W2B)     : w_out [K][1024] -> w2t [1024][K] fp16
// ---------------------------------------------------------------------------
#define XB   (NTOK * HID / 4 / 256)     // 4096 blocks of 256 thr, 1 float4 each
#define W1B  ((3 * HID / 32) * (HID / 32))   // 96*32 = 3072
#define W2B  ((HID / 32) * (HID / 32))       // 32*32 = 1024

__global__ void prepass_kernel(const float* __restrict__ x,  __half* __restrict__ xh,
                               const float* __restrict__ w1, __half* __restrict__ w1t,
                               const float* __restrict__ w2, __half* __restrict__ w2t)
{
    __shared__ float t[32][33];
    int blk = blockIdx.x;
    if (blk < XB) {
        int i = blk * 256 + threadIdx.x;
        float4 v = reinterpret_cast<const float4*>(x)[i];
        __half2 h0 = __float22half2_rn(make_float2(v.x, v.y));
        __half2 h1 = __float22half2_rn(make_float2(v.z, v.w));
        reinterpret_cast<uint2*>(xh)[i] =
            make_uint2(*reinterpret_cast<uint32_t*>(&h0), *reinterpret_cast<uint32_t*>(&h1));
        return;
    }
    const float* in;
    __half* out;
    int N, bi;
    if (blk < XB + W1B) { in = w1; out = w1t; N = 3 * HID; bi = blk - XB; }
    else                { in = w2; out = w2t; N = HID;     bi = blk - XB - W1B; }
    const int nBlocks = N / 32;
    const int n0 = (bi % nBlocks) * 32, k0 = (bi / nBlocks) * 32;
    const int tx = threadIdx.x & 31, ty = threadIdx.x >> 5;   // 32 x 8
    #pragma unroll
    for (int i = 0; i < 4; i++)
        t[ty + i * 8][tx] = in[(size_t)(k0 + ty + i * 8) * N + n0 + tx];
    __syncthreads();
    #pragma unroll
    for (int i = 0; i < 4; i++)
        out[(size_t)(n0 + ty + i * 8) * HID + k0 + tx] = __float2half_rn(t[tx][ty + i * 8]);
}

// ---------------------------------------------------------------------------
// FP16 GEMM (UNCHANGED from R16): 128x256 CTA, BK=64, ldmatrix, 2-stage.
// ---------------------------------------------------------------------------
#define GAH 72
#define GBH 72
#define STAGE_H (128*GAH + 256*GBH)            // halfs per stage = 27648
#define GEMM_SMEM (2 * STAGE_H * 2)            // 110592 B

__global__ __launch_bounds__(256, 1) void gemm_h(
    const __half* __restrict__ A, const __half* __restrict__ Bt,
    const float* __restrict__ bias,
    float* __restrict__ Cf, __half* __restrict__ Ch, __half* __restrict__ vt,
    int M, int N, int K, int mode)
{
    extern __shared__ __half smh[];

    const int tid  = threadIdx.x;
    const int warp = tid >> 5, lane = tid & 31;
    const int wm = warp >> 2, wn = warp & 3;
    const int g2 = lane >> 2, t4 = lane & 3;
    const int quad = lane >> 3, tin = lane & 7;
    const int lrow = (quad & 1) * 8 + tin;
    const int lcol = (quad >> 1) * 8;
    const int cRow = blockIdx.y, cCol = blockIdx.x;

    const __half* Ab = A + (size_t)cRow * 128 * K;
    const __half* Bb = Bt + (size_t)cCol * 256 * K;

    float c[4][8][4];
    #pragma unroll
    for (int mf = 0; mf < 4; mf++)
        #pragma unroll
        for (int nf = 0; nf < 8; nf++)
            #pragma unroll
            for (int i = 0; i < 4; i++) c[mf][nf][i] = 0.f;

    const int nk = K >> 6;

    {
        __half* Ad = smh;
        __half* Bd = smh + 128 * GAH;
        #pragma unroll
        for (int i = 0; i < 4; i++) {
            int idx = tid + i * 256;
            int r = idx >> 3, p = idx & 7;
            CP16(smem_u32(Ad + r * GAH + p * 8), Ab + (size_t)r * K + p * 8);
        }
        #pragma unroll
        for (int i = 0; i < 8; i++) {
            int idx = tid + i * 256;
            int r = idx >> 3, p = idx & 7;
            CP16(smem_u32(Bd + r * GBH + p * 8), Bb + (size_t)r * K + p * 8);
        }
        CP_COMMIT();
    }

    for (int it = 0; it < nk; it++) {
        CP_WAIT0();
        __syncthreads();

        if (it + 1 < nk) {
            const int k0 = (it + 1) << 6;
            __half* Ad = smh + ((it + 1) & 1) * STAGE_H;
            __half* Bd = Ad + 128 * GAH;
            #pragma unroll
            for (int i = 0; i < 4; i++) {
                int idx = tid + i * 256;
                int r = idx >> 3, p = idx & 7;
                CP16(smem_u32(Ad + r * GAH + p * 8), Ab + (size_t)r * K + k0 + p * 8);
            }
            #pragma unroll
            for (int i = 0; i < 8; i++) {
                int idx = tid + i * 256;
                int r = idx >> 3, p = idx & 7;
                CP16(smem_u32(Bd + r * GBH + p * 8), Bb + (size_t)r * K + k0 + p * 8);
            }
            CP_COMMIT();
        }

        const __half* Ac = smh + (it & 1) * STAGE_H;
        const __half* Bc = Ac + 128 * GAH;

        #pragma unroll
        for (int ks = 0; ks < 4; ks++) {
            const int k = ks * 16;
            uint32_t a[4][4], b[8][2];
            #pragma unroll
            for (int mf = 0; mf < 4; mf++) {
                uint32_t addr = smem_u32(Ac + (wm * 64 + mf * 16 + lrow) * GAH + k + lcol);
                LDSM4(a[mf][0], a[mf][1], a[mf][2], a[mf][3], addr);
            }
            #pragma unroll
            for (int nfp = 0; nfp < 4; nfp++) {
                uint32_t addr = smem_u32(Bc + (wn * 64 + nfp * 16 + lrow) * GBH + k + lcol);
                LDSM4(b[2 * nfp][0], b[2 * nfp + 1][0], b[2 * nfp][1], b[2 * nfp + 1][1], addr);
            }
            #pragma unroll
            for (int mf = 0; mf < 4; mf++)
                #pragma unroll
                for (int nf = 0; nf < 8; nf++)
                    mma16(c[mf][nf], a[mf][0], a[mf][1], a[mf][2], a[mf][3],
                          b[nf][0], b[nf][1]);
        }
    }

    #pragma unroll
    for (int nf = 0; nf < 8; nf++) {
        int col = cCol * 256 + wn * 64 + nf * 8 + t4 * 2;
        float b0 = bias[col], b1 = bias[col + 1];
        #pragma unroll
        for (int mf = 0; mf < 4; mf++) {
            int r0 = cRow * 128 + wm * 64 + mf * 16 + g2;
            float v00 = c[mf][nf][0] + b0, v01 = c[mf][nf][1] + b1;
            float v10 = c[mf][nf][2] + b0, v11 = c[mf][nf][3] + b1;
            if (mode == 0) {
                *reinterpret_cast<float2*>(Cf + (size_t)r0 * N + col)       = make_float2(v00, v01);
                *reinterpret_cast<float2*>(Cf + (size_t)(r0 + 8) * N + col) = make_float2(v10, v11);
            } else {
                if (col < 2048) {
                    __half2 h0 = __float22half2_rn(make_float2(v00, v01));
                    __half2 h1 = __float22half2_rn(make_float2(v10, v11));
                    *reinterpret_cast<__half2*>(Ch + (size_t)r0 * 2048 + col)       = h0;
                    *reinterpret_cast<__half2*>(Ch + (size_t)(r0 + 8) * 2048 + col) = h1;
                } else {
                    int hh = (col - 2048) >> 6, d = (col - 2048) & 63;
                    int b0i = r0 >> 11, s0 = r0 & 2047;
                    int b1i = (r0 + 8) >> 11, s1 = (r0 + 8) & 2047;
                    size_t base0 = ((size_t)(b0i * NHEAD + hh) * HDIM + d) * SEQ;
                    size_t base1 = ((size_t)(b1i * NHEAD + hh) * HDIM + d) * SEQ;
                    vt[base0 + s0]       = __float2half_rn(v00);
                    vt[base0 + SEQ + s0] = __float2half_rn(v01);
                    vt[base1 + s1]       = __float2half_rn(v10);
                    vt[base1 + SEQ + s1] = __float2half_rn(v11);
                }
            }
        }
    }
}

// ---------------------------------------------------------------------------
// FP16 causal flash attention: BQ=128, BKV=128, 256 threads (8 warps).
// Half the tile iterations of R16: per-tile fixed costs (barriers, shfl
// reductions, O-rescale) halve. Q frags in registers; P register-only.
// ---------------------------------------------------------------------------
#define BQ  128
#define BKV 128
#define QH_S 72
#define KH_S 72
#define VH_S 136
#define SCALE_L2E 0.18033688011112042f   // 0.125 * log2(e)
// Qs 128*72 + Ks 2*128*72 + Vst 2*64*136 halfs
#define FLASH_SMEM ((128*QH_S + 2*128*KH_S + 2*64*VH_S) * 2)  // 90112 B

__global__ __launch_bounds__(256, 1) void flash_h(
    const __half* __restrict__ qkvh, const __half* __restrict__ vt,
    __half* __restrict__ attn_out)
{
    extern __shared__ __half smh[];
    __half* Qs  = smh;                      // [128][72]
    __half* Ks  = Qs + 128 * QH_S;          // [2][128][72]
    __half* Vst = Ks + 2 * 128 * KH_S;      // [2][64][136]  (Vst[d][kv 128])

    const int qb = gridDim.x - 1 - blockIdx.x;   // heavy blocks first
    const int h = blockIdx.y, b = blockIdx.z;
    const int tid = threadIdx.x, warp = tid >> 5, lane = tid & 31;
    const int g2 = lane >> 2, t4 = lane & 3;
    const int quad = lane >> 3, tin = lane & 7;
    const int lrow = (quad & 1) * 8 + tin;
    const int lcol = (quad >> 1) * 8;
    const int q0 = qb * BQ;
    const size_t vtbase = (size_t)(b * NHEAD + h) * HDIM * SEQ;

    // Q tile: 128x64 fp16, scaled by 0.125*log2e
    {
        const __half2 sc2 = __float2half2_rn(SCALE_L2E);
        #pragma unroll
        for (int i = 0; i < 4; i++) {
            int idx = tid + i * 256;
            int r = idx >> 3, p = idx & 7;
            const __half2* src = reinterpret_cast<const __half2*>(
                qkvh + (size_t)(b * SEQ + q0 + r) * 2048 + h * 64 + p * 8);
            __half2* dst = reinterpret_cast<__half2*>(Qs + r * QH_S + p * 8);
            dst[0] = __hmul2(src[0], sc2);
            dst[1] = __hmul2(src[1], sc2);
            dst[2] = __hmul2(src[2], sc2);
            dst[3] = __hmul2(src[3], sc2);
        }
    }

    // prefetch KV tile 0: K 128 rows x 64 hd; Vt 64 dims x 128 kv
    #pragma unroll
    for (int i = 0; i < 4; i++) {
        int idx = tid + i * 256;                 // 1024 chunks
        int r = idx >> 3, p = idx & 7;
        CP16(smem_u32(Ks + r * KH_S + p * 8),
             qkvh + (size_t)(b * SEQ + r) * 2048 + 1024 + h * 64 + p * 8);
    }
    #pragma unroll
    for (int i = 0; i < 4; i++) {
        int idx = tid + i * 256;                 // 1024 chunks: 64 rows x 16 pieces
        int r = idx >> 4, p = idx & 15;
        CP16(smem_u32(Vst + r * VH_S + p * 8), vt + vtbase + (size_t)r * SEQ + p * 8);
    }
    CP_COMMIT();

    __syncthreads();   // Q smem complete -> fragment preload
    uint32_t qa[4][4];
    #pragma unroll
    for (int ks = 0; ks < 4; ks++) {
        uint32_t addr = smem_u32(Qs + (warp * 16 + lrow) * QH_S + ks * 16 + lcol);
        LDSM4(qa[ks][0], qa[ks][1], qa[ks][2], qa[ks][3], addr);
    }

    const int r0l = warp * 16 + g2;
    const int grow0 = q0 + r0l, grow1 = grow0 + 8;
    float m0 = -1e30f, m1 = -1e30f, l0 = 0.f, l1 = 0.f;
    float o[8][4];
    #pragma unroll
    for (int nf = 0; nf < 8; nf++)
        #pragma unroll
        for (int i = 0; i < 4; i++) o[nf][i] = 0.f;

    const int nkv = qb + 1;    // 128-wide tiles covering [0, q0+127]

    for (int t = 0; t < nkv; t++) {
        CP_WAIT0();
        __syncthreads();

        if (t + 1 < nkv) {
            const int kv1 = (t + 1) * BKV;
            __half* Kd = Ks + ((t + 1) & 1) * 128 * KH_S;
            __half* Vd = Vst + ((t + 1) & 1) * 64 * VH_S;
            #pragma unroll
            for (int i = 0; i < 4; i++) {
                int idx = tid + i * 256;
                int r = idx >> 3, p = idx & 7;
                CP16(smem_u32(Kd + r * KH_S + p * 8),
                     qkvh + (size_t)(b * SEQ + kv1 + r) * 2048 + 1024 + h * 64 + p * 8);
            }
            #pragma unroll
            for (int i = 0; i < 4; i++) {
                int idx = tid + i * 256;
                int r = idx >> 4, p = idx & 15;
                CP16(smem_u32(Vd + r * VH_S + p * 8),
                     vt + vtbase + (size_t)r * SEQ + kv1 + p * 8);
            }
            CP_COMMIT();
        }

        const __half* Kc = Ks + (t & 1) * 128 * KH_S;
        const __half* Vc = Vst + (t & 1) * 64 * VH_S;

        // ---- S = Q @ K^T : 16 col-fragments (128 cols), 4 k16 steps ----
        float s[16][4];
        #pragma unroll
        for (int nf = 0; nf < 16; nf++)
            #pragma unroll
            for (int i = 0; i < 4; i++) s[nf][i] = 0.f;

        #pragma unroll
        for (int ks = 0; ks < 4; ks++) {
            const int k = ks * 16;
            uint32_t kb[16][2];
            #pragma unroll
            for (int nfp = 0; nfp < 8; nfp++) {
                uint32_t addr = smem_u32(Kc + (nfp * 16 + lrow) * KH_S + k + lcol);
                LDSM4(kb[2 * nfp][0], kb[2 * nfp + 1][0],
                      kb[2 * nfp][1], kb[2 * nfp + 1][1], addr);
            }
            #pragma unroll
            for (int nf = 0; nf < 16; nf++)
                mma16(s[nf], qa[ks][0], qa[ks][1], qa[ks][2], qa[ks][3],
                      kb[nf][0], kb[nf][1]);
        }

        // ---- mask + quad row max ----
        const bool nm = (t == nkv - 1);
        float mx0 = -1e30f, mx1 = -1e30f;
        #pragma unroll
        for (int nf = 0; nf < 16; nf++) {
            #pragma unroll
            for (int j = 0; j < 2; j++) {
                int gc = t * BKV + nf * 8 + t4 * 2 + j;
                if (nm && gc > grow0) s[nf][j]     = -1e30f;
                if (nm && gc > grow1) s[nf][2 + j] = -1e30f;
                mx0 = fmaxf(mx0, s[nf][j]);
                mx1 = fmaxf(mx1, s[nf][2 + j]);
            }
        }
        mx0 = fmaxf(mx0, __shfl_xor_sync(0xffffffffu, mx0, 1));
        mx0 = fmaxf(mx0, __shfl_xor_sync(0xffffffffu, mx0, 2));
        mx1 = fmaxf(mx1, __shfl_xor_sync(0xffffffffu, mx1, 1));
        mx1 = fmaxf(mx1, __shfl_xor_sync(0xffffffffu, mx1, 2));

        const float mn0 = fmaxf(m0, mx0);
        const float mn1 = fmaxf(m1, mx1);
        const float a0s = ex2(m0 - mn0);
        const float a1s = ex2(m1 - mn1);

        // ---- P = ex2.f16x2 straight into PV A-fragments ----
        uint32_t pf0[16], pf1[16];
        float ps0 = 0.f, ps1 = 0.f;
        #pragma unroll
        for (int nf = 0; nf < 16; nf++) {
            __half2 e0 = h2ex2(__floats2half2_rn(s[nf][0] - mn0, s[nf][1] - mn0));
            __half2 e1 = h2ex2(__floats2half2_rn(s[nf][2] - mn1, s[nf][3] - mn1));
            pf0[nf] = h2bits(e0);
            pf1[nf] = h2bits(e1);
            float2 f0 = __half22float2(e0);
            float2 f1 = __half22float2(e1);
            ps0 += f0.x + f0.y;
            ps1 += f1.x + f1.y;
        }
        ps0 += __shfl_xor_sync(0xffffffffu, ps0, 1);
        ps0 += __shfl_xor_sync(0xffffffffu, ps0, 2);
        ps1 += __shfl_xor_sync(0xffffffffu, ps1, 1);
        ps1 += __shfl_xor_sync(0xffffffffu, ps1, 2);
        l0 = l0 * a0s + ps0;
        l1 = l1 * a1s + ps1;
        m0 = mn0; m1 = mn1;

        #pragma unroll
        for (int nf = 0; nf < 8; nf++) {
            o[nf][0] *= a0s; o[nf][1] *= a0s;
            o[nf][2] *= a1s; o[nf][3] *= a1s;
        }

        // ---- O += P @ V : k-dim = 128 kv (8 k16 steps), n = 64 dims ----
        #pragma unroll
        for (int ks = 0; ks < 8; ks++) {
            const int k = ks * 16;
            uint32_t vb[8][2];
            #pragma unroll
            for (int nfp = 0; nfp < 4; nfp++) {
                uint32_t addr = smem_u32(Vc + (nfp * 16 + lrow) * VH_S + k + lcol);
                LDSM4(vb[2 * nfp][0], vb[2 * nfp + 1][0],
                      vb[2 * nfp][1], vb[2 * nfp + 1][1], addr);
            }
            #pragma unroll
            for (int nf = 0; nf < 8; nf++)
                mma16(o[nf], pf0[2 * ks], pf1[2 * ks], pf0[2 * ks + 1], pf1[2 * ks + 1],
                      vb[nf][0], vb[nf][1]);
        }
    }

    const float inv0 = 1.f / l0, inv1 = 1.f / l1;
    #pragma unroll
    for (int nf = 0; nf < 8; nf++) {
        int cc = nf * 8 + t4 * 2;
        __half* p0 = attn_out + (size_t)(b * SEQ + grow0) * HID + h * 64 + cc;
        __half* p1 = attn_out + (size_t)(b * SEQ + grow1) * HID + h * 64 + cc;
        *reinterpret_cast<__half2*>(p0) =
            __float22half2_rn(make_float2(o[nf][0] * inv0, o[nf][1] * inv0));
        *reinterpret_cast<__half2*>(p1) =
            __float22half2_rn(make_float2(o[nf][2] * inv1, o[nf][3] * inv1));
    }
}

// ---------------------------------------------------------------------------
extern "C" void kernel_launch(void* const* d_in, const int* in_sizes, int n_in,
                              void* d_out, int out_size)
{
    const float* x     = (const float*)d_in[0];
    const float* w_qkv = (const float*)d_in[1];
    const float* b_qkv = (const float*)d_in[2];
    const float* w_out = (const float*)d_in[3];
    const float* b_out = (const float*)d_in[4];
    float* out = (float*)d_out;

    __half *xh, *w1t, *w2t, *qkvh, *vt, *attnh;
    cudaGetSymbolAddress((void**)&xh,    g_xh);
    cudaGetSymbolAddress((void**)&w1t,   g_w1t);
    cudaGetSymbolAddress((void**)&w2t,   g_w2t);
    cudaGetSymbolAddress((void**)&qkvh,  g_qkvh);
    cudaGetSymbolAddress((void**)&vt,    g_vt);
    cudaGetSymbolAddress((void**)&attnh, g_attnh);

    cudaFuncSetAttribute(gemm_h,  cudaFuncAttributeMaxDynamicSharedMemorySize, GEMM_SMEM);
    cudaFuncSetAttribute(flash_h, cudaFuncAttributeMaxDynamicSharedMemorySize, FLASH_SMEM);

    // 0) merged prepass: x->fp16, weights->fp16 transposed, ONE launch
    prepass_kernel<<<XB + W1B + W2B, 256>>>(x, xh, w_qkv, w1t, w_out, w2t);

    // 1) qkv = x @ w_qkv + b_qkv  (fp16 out; V transposed)
    dim3 g1(3 * HID / 256, NTOK / 128);
    gemm_h<<<g1, 256, GEMM_SMEM>>>(xh, w1t, b_qkv, nullptr, qkvh, vt,
                                   NTOK, 3 * HID, HID, 1);

    // 2) causal flash attention (BKV=128)
    dim3 g2(SEQ / BQ, NHEAD, BATCH);
    flash_h<<<g2, 256, FLASH_SMEM>>>(qkvh, vt, attnh);

    // 3) out = attn @ w_out + b_out  (fp32 out)
    dim3 g3(HID / 256, NTOK / 128);
    gemm_h<<<g3, 256, GEMM_SMEM>>>(attnh, w2t, b_out, out, nullptr, nullptr,
                                   NTOK, HID, HID, 0);
}